// round 1
// baseline (speedup 1.0000x reference)
#include <cuda_runtime.h>
#include <cstdint>

#define NNODE  6144
#define MAXDEG 192

// ---------------- scratch (device globals: no allocation allowed) -----------
__device__ int   g_deg[NNODE];
__device__ int   g_cols[NNODE * MAXDEG];
__device__ float g_h  [NNODE * 16];   // per-layer transformed features (max H*F = 16)
__device__ float g_es [NNODE * 2];    // source attention logits (max H = 2)
__device__ float g_ed [NNODE * 2];    // dest attention logits
__device__ float g_x  [NNODE * 12];   // activations between layers (max 12)
__device__ float g_out[NNODE * 16];   // final per-node output before sum

// ---------------- CSR build: warp per row, ballot compaction ----------------
__global__ void build_csr(const float* __restrict__ adj) {
    int row  = (blockIdx.x * blockDim.x + threadIdx.x) >> 5;
    int lane = threadIdx.x & 31;
    if (row >= NNODE) return;
    const float4* a4 = reinterpret_cast<const float4*>(adj + (size_t)row * NNODE);
    int* out = g_cols + (size_t)row * MAXDEG;
    int base = 0;
    unsigned lt = (1u << lane) - 1u;
    for (int c0 = 0; c0 < NNODE; c0 += 128) {
        float4 v = __ldg(&a4[(c0 >> 2) + lane]);
        int col0 = c0 + lane * 4;
        float vals[4] = {v.x, v.y, v.z, v.w};
#pragma unroll
        for (int j = 0; j < 4; j++) {
            bool nz = vals[j] > 0.f;
            unsigned m = __ballot_sync(0xffffffffu, nz);
            if (nz) {
                int p = base + __popc(m & lt);
                if (p < MAXDEG) out[p] = col0 + j;
            }
            base += __popc(m);
        }
    }
    if (lane == 0) g_deg[row] = base < MAXDEG ? base : MAXDEG;
}

// ---------------- fused linear: h = x@W, e_src/e_dst dots -------------------
template <int FIN, int H, int F, bool XGLOBAL>
__global__ void linear_kernel(const float* __restrict__ xin,
                              const float* __restrict__ W,
                              const float* __restrict__ a_s,
                              const float* __restrict__ a_d) {
    __shared__ float sW[H * FIN * F];
    __shared__ float sas[H * F];
    __shared__ float sad[H * F];
    for (int i = threadIdx.x; i < H * FIN * F; i += blockDim.x) sW[i] = W[i];
    if (threadIdx.x < H * F) {
        sas[threadIdx.x] = a_s[threadIdx.x];
        sad[threadIdx.x] = a_d[threadIdx.x];
    }
    __syncthreads();
    int n = blockIdx.x * blockDim.x + threadIdx.x;
    if (n >= NNODE) return;
    const float* xp = XGLOBAL ? g_x : xin;
    float xr[FIN];
#pragma unroll
    for (int i = 0; i < FIN; i++) xr[i] = xp[n * FIN + i];
#pragma unroll
    for (int h = 0; h < H; h++) {
        float acc[F];
#pragma unroll
        for (int f = 0; f < F; f++) acc[f] = 0.f;
#pragma unroll
        for (int i = 0; i < FIN; i++) {
            float xv = xr[i];
#pragma unroll
            for (int f = 0; f < F; f++) acc[f] += xv * sW[(h * FIN + i) * F + f];
        }
        float es = 0.f, ed = 0.f;
#pragma unroll
        for (int f = 0; f < F; f++) {
            g_h[n * (H * F) + h * F + f] = acc[f];
            es += acc[f] * sas[h * F + f];
            ed += acc[f] * sad[h * F + f];
        }
        g_es[n * H + h] = es;
        g_ed[n * H + h] = ed;
    }
}

// ---------------- warp-per-node sparse softmax aggregate --------------------
template <int H, int F, bool FINAL>
__global__ void attn_kernel() {
    int warp = (blockIdx.x * blockDim.x + threadIdx.x) >> 5;
    int lane = threadIdx.x & 31;
    if (warp >= NNODE) return;
    const int n = warp;
    const int deg = g_deg[n];
    const int* cols = g_cols + (size_t)n * MAXDEG;

    float es_n[H];
#pragma unroll
    for (int h = 0; h < H; h++) es_n[h] = g_es[n * H + h];

    // pass 1: row max of leaky_relu(e_src + e_dst) over neighbors
    float emax[H];
#pragma unroll
    for (int h = 0; h < H; h++) emax[h] = -1e30f;
    for (int k = lane; k < deg; k += 32) {
        int m = cols[k];
#pragma unroll
        for (int h = 0; h < H; h++) {
            float e = es_n[h] + g_ed[m * H + h];
            e = e > 0.f ? e : 0.2f * e;
            emax[h] = fmaxf(emax[h], e);
        }
    }
#pragma unroll
    for (int h = 0; h < H; h++)
#pragma unroll
        for (int o = 16; o > 0; o >>= 1)
            emax[h] = fmaxf(emax[h], __shfl_xor_sync(0xffffffffu, emax[h], o));

    // pass 2: exp-weight and accumulate neighbor features
    float wsum[H];
    float acc[H * F];
#pragma unroll
    for (int h = 0; h < H; h++) wsum[h] = 0.f;
#pragma unroll
    for (int i = 0; i < H * F; i++) acc[i] = 0.f;

    for (int k = lane; k < deg; k += 32) {
        int m = cols[k];
#pragma unroll
        for (int h = 0; h < H; h++) {
            float e = es_n[h] + g_ed[m * H + h];
            e = e > 0.f ? e : 0.2f * e;
            float w = expf(e - emax[h]);
            wsum[h] += w;
            const float* hp = g_h + m * (H * F) + h * F;
#pragma unroll
            for (int f = 0; f < F; f++) acc[h * F + f] += w * hp[f];
        }
    }
#pragma unroll
    for (int h = 0; h < H; h++)
#pragma unroll
        for (int o = 16; o > 0; o >>= 1)
            wsum[h] += __shfl_xor_sync(0xffffffffu, wsum[h], o);
#pragma unroll
    for (int i = 0; i < H * F; i++)
#pragma unroll
        for (int o = 16; o > 0; o >>= 1)
            acc[i] += __shfl_xor_sync(0xffffffffu, acc[i], o);

    if (lane == 0) {
#pragma unroll
        for (int h = 0; h < H; h++) {
            float inv = 1.f / wsum[h];
#pragma unroll
            for (int f = 0; f < F; f++) {
                float v = acc[h * F + f] * inv;
                if (FINAL) {
                    v = v > 0.f ? v : 0.f;               // relu
                    g_out[n * F + f] = v;
                } else {
                    v = v > 0.f ? v : expm1f(v);          // elu
                    g_x[n * (H * F) + h * F + f] = v;
                }
            }
        }
    }
}

// ---------------- deterministic column sum ----------------------------------
__global__ void reduce_kernel(float* __restrict__ out) {
    int f = blockIdx.x;  // 0..15
    float s = 0.f;
    for (int i = threadIdx.x; i < NNODE; i += blockDim.x) s += g_out[i * 16 + f];
    __shared__ float sh[256];
    sh[threadIdx.x] = s;
    __syncthreads();
    for (int st = 128; st > 0; st >>= 1) {
        if (threadIdx.x < st) sh[threadIdx.x] += sh[threadIdx.x + st];
        __syncthreads();
    }
    if (threadIdx.x == 0) out[f] = sh[0];
}

// ---------------- launch ----------------------------------------------------
extern "C" void kernel_launch(void* const* d_in, const int* in_sizes, int n_in,
                              void* d_out, int out_size) {
    const float* x   = (const float*)d_in[0];
    const float* adj = (const float*)d_in[1];
    const float* W0  = (const float*)d_in[2];
    const float* a0s = (const float*)d_in[3];
    const float* a0d = (const float*)d_in[4];
    const float* W1  = (const float*)d_in[5];
    const float* a1s = (const float*)d_in[6];
    const float* a1d = (const float*)d_in[7];
    const float* W2  = (const float*)d_in[8];
    const float* a2s = (const float*)d_in[9];
    const float* a2d = (const float*)d_in[10];
    float* out = (float*)d_out;

    const int TB = 256;
    const int warp_blocks = NNODE / (TB / 32);  // 768
    const int node_blocks = NNODE / TB;         // 24

    build_csr<<<warp_blocks, TB>>>(adj);

    // layer 0: F_in=64, H=2, F=6
    linear_kernel<64, 2, 6, false><<<node_blocks, TB>>>(x, W0, a0s, a0d);
    attn_kernel<2, 6, false><<<warp_blocks, TB>>>();

    // layer 1: F_in=12, H=2, F=3
    linear_kernel<12, 2, 3, true><<<node_blocks, TB>>>(nullptr, W1, a1s, a1d);
    attn_kernel<2, 3, false><<<warp_blocks, TB>>>();

    // layer 2: F_in=6, H=1, F=16
    linear_kernel<6, 1, 16, true><<<node_blocks, TB>>>(nullptr, W2, a2s, a2d);
    attn_kernel<1, 16, true><<<warp_blocks, TB>>>();

    reduce_kernel<<<16, 256>>>(out);
}

// round 2
// speedup vs baseline: 1.0955x; 1.0955x over previous
#include <cuda_runtime.h>
#include <cstdint>

#define NN     6144
#define MAXDEG 192
#define FULL   0xffffffffu

// ---------------- scratch (device globals; no allocation allowed) -----------
__device__ int   g_deg[NN];
__device__ int   g_cols[NN * MAXDEG];
__device__ float g_h [2][NN * 16];
__device__ float g_es[2][NN * 2];
__device__ float g_ed[2][NN * 2];
__device__ float g_out[NN * 16];
__device__ int   g_counter;   // zero-initialized

// ===================== K1: linear0 + CSR build (fused) =======================
// warp per node. linear0: FIN=64, H=2, F=6 (12 outputs). Then scan adj row.
__global__ void __launch_bounds__(256) k_csr_lin0(
    const float* __restrict__ x, const float* __restrict__ adj,
    const float* __restrict__ W0, const float* __restrict__ a0s,
    const float* __restrict__ a0d)
{
    __shared__ float sW[64 * 12];   // [h][i][f] = (h*64+i)*6+f
    __shared__ float sa[24];        // [0:12) a_src, [12:24) a_dst
    for (int i = threadIdx.x; i < 768; i += 256) sW[i] = W0[i];
    if (threadIdx.x < 12) {
        sa[threadIdx.x]      = a0s[threadIdx.x];
        sa[12 + threadIdx.x] = a0d[threadIdx.x];
    }
    __syncthreads();

    const int node = (blockIdx.x * 256 + threadIdx.x) >> 5;
    const int lane = threadIdx.x & 31;

    // ---- linear0: lane covers inputs (lane, lane+32) ----
    float x0 = x[node * 64 + lane];
    float x1 = x[node * 64 + 32 + lane];
    float acc[12];
#pragma unroll
    for (int h = 0; h < 2; h++)
#pragma unroll
        for (int f = 0; f < 6; f++) {
            int hf = h * 6 + f;
            acc[hf] = x0 * sW[(h * 64 + lane) * 6 + f]
                    + x1 * sW[(h * 64 + lane + 32) * 6 + f];
        }
#pragma unroll
    for (int i = 0; i < 12; i++)
#pragma unroll
        for (int o = 16; o > 0; o >>= 1)
            acc[i] += __shfl_xor_sync(FULL, acc[i], o);

    if (lane == 0) {
        float es0 = 0.f, ed0 = 0.f, es1 = 0.f, ed1 = 0.f;
#pragma unroll
        for (int f = 0; f < 6; f++) {
            es0 += acc[f]     * sa[f];       ed0 += acc[f]     * sa[12 + f];
            es1 += acc[6 + f] * sa[6 + f];   ed1 += acc[6 + f] * sa[18 + f];
        }
#pragma unroll
        for (int i = 0; i < 12; i++) g_h[0][node * 12 + i] = acc[i];
        g_es[0][node * 2]     = es0;  g_es[0][node * 2 + 1] = es1;
        g_ed[0][node * 2]     = ed0;  g_ed[0][node * 2 + 1] = ed1;
    }

    // ---- CSR build (ballot compaction, prefetched) ----
    const float4* a4 = reinterpret_cast<const float4*>(adj + (size_t)node * NN);
    int* outc = g_cols + (size_t)node * MAXDEG;
    int base = 0;
    const unsigned lt = (1u << lane) - 1u;
    float4 v = __ldg(&a4[lane]);
    for (int c0 = 0; c0 < NN; c0 += 128) {
        float4 vn = {0.f, 0.f, 0.f, 0.f};
        if (c0 + 128 < NN) vn = __ldg(&a4[((c0 + 128) >> 2) + lane]);
        float vals[4] = {v.x, v.y, v.z, v.w};
        int col0 = c0 + lane * 4;
#pragma unroll
        for (int j = 0; j < 4; j++) {
            bool nz = vals[j] > 0.f;
            unsigned m = __ballot_sync(FULL, nz);
            if (m) {
                if (nz) {
                    int p = base + __popc(m & lt);
                    if (p < MAXDEG) outc[p] = col0 + j;
                }
                base += __popc(m);
            }
        }
        v = vn;
    }
    if (lane == 0) g_deg[node] = base < MAXDEG ? base : MAXDEG;
}

// ========== K2/K3: attn (layer H,F) + elu + next linear (H2,F2) ==============
// IB = input buffer index, OB = output buffer index. Warp per node.
template <int H, int F, int H2, int F2, int IB, int OB>
__global__ void __launch_bounds__(256) k_attn_lin(
    const float* __restrict__ Wn, const float* __restrict__ nas,
    const float* __restrict__ nad)
{
    constexpr int D = H * F;      // current layer concat dim (next linear FIN)
    constexpr int O = H2 * F2;    // next layer output dim
    __shared__ float sW[H2 * D * F2];
    __shared__ float sa[2 * O];
    __shared__ float sh_h[8][O];  // per-warp new h for es/ed dots
    for (int i = threadIdx.x; i < H2 * D * F2; i += 256) sW[i] = Wn[i];
    if (threadIdx.x < O) {
        sa[threadIdx.x]     = nas[threadIdx.x];
        sa[O + threadIdx.x] = nad[threadIdx.x];
    }
    __syncthreads();

    const int node = (blockIdx.x * 256 + threadIdx.x) >> 5;
    const int lane = threadIdx.x & 31;
    const int wid  = threadIdx.x >> 5;
    const int deg  = g_deg[node];
    const int* cols = g_cols + (size_t)node * MAXDEG;

    float es_n[H];
#pragma unroll
    for (int h = 0; h < H; h++) es_n[h] = g_es[IB][node * H + h];

    float wsum[H];
    float acc[D];
#pragma unroll
    for (int h = 0; h < H; h++) wsum[h] = 0.f;
#pragma unroll
    for (int i = 0; i < D; i++) acc[i] = 0.f;

    for (int k = lane; k < deg; k += 32) {
        int m = cols[k];
#pragma unroll
        for (int h = 0; h < H; h++) {
            float e = es_n[h] + g_ed[IB][m * H + h];
            e = e > 0.f ? e : 0.2f * e;
            float w = expf(e);
            wsum[h] += w;
            const float* hp = &g_h[IB][m * D + h * F];
#pragma unroll
            for (int f = 0; f < F; f++) acc[h * F + f] += w * hp[f];
        }
    }
#pragma unroll
    for (int h = 0; h < H; h++)
#pragma unroll
        for (int o = 16; o > 0; o >>= 1)
            wsum[h] += __shfl_xor_sync(FULL, wsum[h], o);
#pragma unroll
    for (int i = 0; i < D; i++)
#pragma unroll
        for (int o = 16; o > 0; o >>= 1)
            acc[i] += __shfl_xor_sync(FULL, acc[i], o);

    // elu on every lane (all lanes hold the full reduction; static indexing)
    float xn[D];
#pragma unroll
    for (int h = 0; h < H; h++) {
        float inv = 1.f / wsum[h];
#pragma unroll
        for (int f = 0; f < F; f++) {
            float vv = acc[h * F + f] * inv;
            xn[h * F + f] = vv > 0.f ? vv : expm1f(vv);
        }
    }

    // next-layer linear: lane j < O computes output j
    if (lane < O) {
        int h2 = lane / F2, f2 = lane % F2;
        float s = 0.f;
#pragma unroll
        for (int i = 0; i < D; i++) s += xn[i] * sW[(h2 * D + i) * F2 + f2];
        g_h[OB][node * O + lane] = s;
        sh_h[wid][lane] = s;
    }
    __syncwarp();
    if (lane < H2) {
        float es = 0.f, ed = 0.f;
        for (int f2 = 0; f2 < F2; f2++) {
            float hv = sh_h[wid][lane * F2 + f2];
            es += hv * sa[lane * F2 + f2];
            ed += hv * sa[O + lane * F2 + f2];
        }
        g_es[OB][node * H2 + lane] = es;
        g_ed[OB][node * H2 + lane] = ed;
    }
}

// ===== K4: final attn (H=1,F=16) + relu + deterministic last-block reduce ====
__global__ void __launch_bounds__(256) k_attn_final(float* __restrict__ out)
{
    const int node = (blockIdx.x * 256 + threadIdx.x) >> 5;
    const int lane = threadIdx.x & 31;
    const int deg  = g_deg[node];
    const int* cols = g_cols + (size_t)node * MAXDEG;

    const float es_n = g_es[0][node];
    float wsum = 0.f;
    float acc[16];
#pragma unroll
    for (int i = 0; i < 16; i++) acc[i] = 0.f;

    for (int k = lane; k < deg; k += 32) {
        int m = cols[k];
        float e = es_n + g_ed[0][m];
        e = e > 0.f ? e : 0.2f * e;
        float w = expf(e);
        wsum += w;
        const float* hp = &g_h[0][m * 16];
#pragma unroll
        for (int f = 0; f < 16; f++) acc[f] += w * hp[f];
    }
#pragma unroll
    for (int o = 16; o > 0; o >>= 1) wsum += __shfl_xor_sync(FULL, wsum, o);
#pragma unroll
    for (int i = 0; i < 16; i++)
#pragma unroll
        for (int o = 16; o > 0; o >>= 1)
            acc[i] += __shfl_xor_sync(FULL, acc[i], o);

    if (lane == 0) {
        float inv = 1.f / wsum;
#pragma unroll
        for (int f = 0; f < 16; f++) {
            float v = acc[f] * inv;
            g_out[node * 16 + f] = v > 0.f ? v : 0.f;
        }
    }

    // ---- last-block fixed-order reduction ----
    __syncthreads();
    __threadfence();
    __shared__ bool isLast;
    if (threadIdx.x == 0)
        isLast = (atomicAdd(&g_counter, 1) == (int)gridDim.x - 1);
    __syncthreads();
    if (isLast) {
        int f = threadIdx.x & 15, g = threadIdx.x >> 4;   // 16 groups x 16 features
        float s = 0.f;
        for (int i = g; i < NN; i += 16) s += g_out[i * 16 + f];
        __shared__ float red[256];
        red[threadIdx.x] = s;
        __syncthreads();
        if (threadIdx.x < 16) {
            float t = 0.f;
            for (int gg = 0; gg < 16; gg++) t += red[gg * 16 + threadIdx.x];
            out[threadIdx.x] = t;
        }
        if (threadIdx.x == 0) g_counter = 0;   // reset for next replay
    }
}

// ---------------- launch ----------------------------------------------------
extern "C" void kernel_launch(void* const* d_in, const int* in_sizes, int n_in,
                              void* d_out, int out_size) {
    const float* x   = (const float*)d_in[0];
    const float* adj = (const float*)d_in[1];
    const float* W0  = (const float*)d_in[2];
    const float* a0s = (const float*)d_in[3];
    const float* a0d = (const float*)d_in[4];
    const float* W1  = (const float*)d_in[5];
    const float* a1s = (const float*)d_in[6];
    const float* a1d = (const float*)d_in[7];
    const float* W2  = (const float*)d_in[8];
    const float* a2s = (const float*)d_in[9];
    const float* a2d = (const float*)d_in[10];
    float* out = (float*)d_out;

    const int G = NN / 8;   // 768 blocks, warp per node

    k_csr_lin0<<<G, 256>>>(x, adj, W0, a0s, a0d);
    // attn layer0 (H=2,F=6) + linear1 (H2=2,F2=3): buf0 -> buf1
    k_attn_lin<2, 6, 2, 3, 0, 1><<<G, 256>>>(W1, a1s, a1d);
    // attn layer1 (H=2,F=3) + linear2 (H2=1,F2=16): buf1 -> buf0
    k_attn_lin<2, 3, 1, 16, 1, 0><<<G, 256>>>(W2, a2s, a2d);
    // final attn + relu + reduce
    k_attn_final<<<G, 256>>>(out);
}

// round 3
// speedup vs baseline: 1.4357x; 1.3106x over previous
#include <cuda_runtime.h>
#include <cstdint>

#define NN     6144
#define MAXDEG 192
#define FULL   0xffffffffu
#define GRID   768

// ---------------- scratch (device globals; no allocation allowed) -----------
__device__ int   g_deg[NN];
__device__ int   g_cols[NN * MAXDEG];
// padded per-node state rows (16B aligned, ed/es embedded for 1-gather access)
// layer0: stride 16: [h0..h11, ed0, ed1, es0, es1]
// layer1: stride 12: [h0..h5, ed0, ed1, es0, es1, pad, pad]
// layer2: stride 20: [h0..h15, ed, es, pad, pad]
__device__ __align__(16) float g_h0[NN * 16];
__device__ __align__(16) float g_h1[NN * 12];
__device__ __align__(16) float g_h2[NN * 20];
__device__ float g_part[GRID * 16];
__device__ int   g_counter;   // zero-initialized

#define XOR_RED(v) { _Pragma("unroll") for (int _o = 16; _o > 0; _o >>= 1) (v) += __shfl_xor_sync(FULL, (v), _o); }

// ===================== K1: linear0 + CSR build (fused) =======================
__global__ void __launch_bounds__(256) k_csr_lin0(
    const float* __restrict__ x, const float* __restrict__ adj,
    const float* __restrict__ W0, const float* __restrict__ a0s,
    const float* __restrict__ a0d)
{
    __shared__ float sW[64 * 12];
    __shared__ float sa[24];
    for (int i = threadIdx.x; i < 768; i += 256) sW[i] = W0[i];
    if (threadIdx.x < 12) {
        sa[threadIdx.x]      = a0s[threadIdx.x];
        sa[12 + threadIdx.x] = a0d[threadIdx.x];
    }
    __syncthreads();

    const int node = (blockIdx.x * 256 + threadIdx.x) >> 5;
    const int lane = threadIdx.x & 31;

    // ---- linear0 ----
    float x0 = x[node * 64 + lane];
    float x1 = x[node * 64 + 32 + lane];
    float acc[12];
#pragma unroll
    for (int h = 0; h < 2; h++)
#pragma unroll
        for (int f = 0; f < 6; f++) {
            int hf = h * 6 + f;
            acc[hf] = x0 * sW[(h * 64 + lane) * 6 + f]
                    + x1 * sW[(h * 64 + lane + 32) * 6 + f];
        }
#pragma unroll
    for (int i = 0; i < 12; i++) XOR_RED(acc[i]);

    if (lane == 0) {
        float es0 = 0.f, ed0 = 0.f, es1 = 0.f, ed1 = 0.f;
#pragma unroll
        for (int f = 0; f < 6; f++) {
            es0 += acc[f]     * sa[f];       ed0 += acc[f]     * sa[12 + f];
            es1 += acc[6 + f] * sa[6 + f];   ed1 += acc[6 + f] * sa[18 + f];
        }
        float4* row = reinterpret_cast<float4*>(&g_h0[node * 16]);
        row[0] = make_float4(acc[0], acc[1], acc[2],  acc[3]);
        row[1] = make_float4(acc[4], acc[5], acc[6],  acc[7]);
        row[2] = make_float4(acc[8], acc[9], acc[10], acc[11]);
        row[3] = make_float4(ed0, ed1, es0, es1);
    }

    // ---- CSR build ----
    const float4* a4 = reinterpret_cast<const float4*>(adj + (size_t)node * NN);
    int* outc = g_cols + (size_t)node * MAXDEG;
    int base = 0;
    const unsigned lt = (1u << lane) - 1u;
    float4 v = __ldg(&a4[lane]);
    for (int c0 = 0; c0 < NN; c0 += 128) {
        float4 vn = {0.f, 0.f, 0.f, 0.f};
        if (c0 + 128 < NN) vn = __ldg(&a4[((c0 + 128) >> 2) + lane]);
        float vals[4] = {v.x, v.y, v.z, v.w};
        int col0 = c0 + lane * 4;
#pragma unroll
        for (int j = 0; j < 4; j++) {
            bool nz = vals[j] > 0.f;
            unsigned m = __ballot_sync(FULL, nz);
            if (m) {
                if (nz) {
                    int p = base + __popc(m & lt);
                    if (p < MAXDEG) outc[p] = col0 + j;
                }
                base += __popc(m);
            }
        }
        v = vn;
    }
    if (lane == 0) g_deg[node] = base < MAXDEG ? base : MAXDEG;
}

// ======== K2: attn layer0 (H=2,F=6) + elu + linear1 (H2=2,F2=3) ==============
__global__ void __launch_bounds__(256) k_attn0(
    const float* __restrict__ W1, const float* __restrict__ a1s,
    const float* __restrict__ a1d)
{
    __shared__ float sW[72];     // [2][12][3]
    __shared__ float sa[12];     // a1s(6), a1d(6)
    __shared__ float shh[8][6];
    if (threadIdx.x < 72) sW[threadIdx.x] = W1[threadIdx.x];
    if (threadIdx.x < 6) {
        sa[threadIdx.x]     = a1s[threadIdx.x];
        sa[6 + threadIdx.x] = a1d[threadIdx.x];
    }
    __syncthreads();

    const int node = (blockIdx.x * 256 + threadIdx.x) >> 5;
    const int lane = threadIdx.x & 31;
    const int wid  = threadIdx.x >> 5;
    const int deg  = g_deg[node];
    const int* __restrict__ cols = g_cols + (size_t)node * MAXDEG;

    const float es0 = g_h0[node * 16 + 14];
    const float es1 = g_h0[node * 16 + 15];

    float4 a0 = {0,0,0,0}, a1 = {0,0,0,0}, a2 = {0,0,0,0};
    float ws0 = 0.f, ws1 = 0.f;

    for (int k = lane; k < deg; k += 32) {
        int m = cols[k];
        const float4* r = reinterpret_cast<const float4*>(&g_h0[m * 16]);
        float4 r0 = r[0], r1 = r[1], r2 = r[2], r3 = r[3];
        float e0 = es0 + r3.x; e0 = e0 > 0.f ? e0 : 0.2f * e0;
        float e1 = es1 + r3.y; e1 = e1 > 0.f ? e1 : 0.2f * e1;
        float w0 = __expf(e0), w1 = __expf(e1);
        ws0 += w0; ws1 += w1;
        a0.x += w0 * r0.x; a0.y += w0 * r0.y; a0.z += w0 * r0.z; a0.w += w0 * r0.w;
        a1.x += w0 * r1.x; a1.y += w0 * r1.y; a1.z += w1 * r1.z; a1.w += w1 * r1.w;
        a2.x += w1 * r2.x; a2.y += w1 * r2.y; a2.z += w1 * r2.z; a2.w += w1 * r2.w;
    }
    float red[14] = {a0.x,a0.y,a0.z,a0.w, a1.x,a1.y,a1.z,a1.w,
                     a2.x,a2.y,a2.z,a2.w, ws0, ws1};
#pragma unroll
    for (int i = 0; i < 14; i++) XOR_RED(red[i]);

    const float inv0 = 1.f / red[12], inv1 = 1.f / red[13];
    float xn[12];
#pragma unroll
    for (int i = 0; i < 12; i++) {
        float vv = red[i] * (i < 6 ? inv0 : inv1);
        xn[i] = vv > 0.f ? vv : expm1f(vv);
    }

    if (lane < 6) {
        int h2 = lane / 3, f2 = lane % 3;
        float s = 0.f;
#pragma unroll
        for (int i = 0; i < 12; i++) s += xn[i] * sW[(h2 * 12 + i) * 3 + f2];
        g_h1[node * 12 + lane] = s;
        shh[wid][lane] = s;
    }
    __syncwarp();
    if (lane < 2) {
        float es = 0.f, ed = 0.f;
#pragma unroll
        for (int f2 = 0; f2 < 3; f2++) {
            float hv = shh[wid][lane * 3 + f2];
            es += hv * sa[lane * 3 + f2];
            ed += hv * sa[6 + lane * 3 + f2];
        }
        g_h1[node * 12 + 6 + lane] = ed;   // slots 6,7
        g_h1[node * 12 + 8 + lane] = es;   // slots 8,9
    }
}

// ======== K3: attn layer1 (H=2,F=3) + elu + linear2 (H2=1,F2=16) =============
__global__ void __launch_bounds__(256) k_attn1(
    const float* __restrict__ W2, const float* __restrict__ a2s,
    const float* __restrict__ a2d)
{
    __shared__ float sW[96];     // [6][16]
    __shared__ float sa2[32];    // a2d(16), a2s(16)
    __shared__ float shh[8][16];
    if (threadIdx.x < 96) sW[threadIdx.x] = W2[threadIdx.x];
    if (threadIdx.x < 16) {
        sa2[threadIdx.x]      = a2d[threadIdx.x];
        sa2[16 + threadIdx.x] = a2s[threadIdx.x];
    }
    __syncthreads();

    const int node = (blockIdx.x * 256 + threadIdx.x) >> 5;
    const int lane = threadIdx.x & 31;
    const int wid  = threadIdx.x >> 5;
    const int deg  = g_deg[node];
    const int* __restrict__ cols = g_cols + (size_t)node * MAXDEG;

    const float es0 = g_h1[node * 12 + 8];
    const float es1 = g_h1[node * 12 + 9];

    float acc[6] = {0,0,0,0,0,0};
    float ws0 = 0.f, ws1 = 0.f;

    for (int k = lane; k < deg; k += 32) {
        int m = cols[k];
        const float4* r = reinterpret_cast<const float4*>(&g_h1[m * 12]);
        float4 r0 = r[0], r1 = r[1];
        float e0 = es0 + r1.z; e0 = e0 > 0.f ? e0 : 0.2f * e0;
        float e1 = es1 + r1.w; e1 = e1 > 0.f ? e1 : 0.2f * e1;
        float w0 = __expf(e0), w1 = __expf(e1);
        ws0 += w0; ws1 += w1;
        acc[0] += w0 * r0.x; acc[1] += w0 * r0.y; acc[2] += w0 * r0.z;
        acc[3] += w1 * r0.w; acc[4] += w1 * r1.x; acc[5] += w1 * r1.y;
    }
    float red[8] = {acc[0],acc[1],acc[2],acc[3],acc[4],acc[5], ws0, ws1};
#pragma unroll
    for (int i = 0; i < 8; i++) XOR_RED(red[i]);

    const float inv0 = 1.f / red[6], inv1 = 1.f / red[7];
    float xn[6];
#pragma unroll
    for (int i = 0; i < 6; i++) {
        float vv = red[i] * (i < 3 ? inv0 : inv1);
        xn[i] = vv > 0.f ? vv : expm1f(vv);
    }

    if (lane < 16) {
        float s = 0.f;
#pragma unroll
        for (int i = 0; i < 6; i++) s += xn[i] * sW[i * 16 + lane];
        g_h2[node * 20 + lane] = s;
        shh[wid][lane] = s;
    }
    __syncwarp();
    if (lane < 2) {
        float d = 0.f;
#pragma unroll
        for (int f = 0; f < 16; f++) d += shh[wid][f] * sa2[lane * 16 + f];
        g_h2[node * 20 + 16 + lane] = d;   // slot 16 = ed, slot 17 = es
    }
}

// ===== K4: final attn (H=1,F=16) + relu + hierarchical deterministic sum =====
__global__ void __launch_bounds__(256) k_attn_final(float* __restrict__ out)
{
    __shared__ float sblk[8][16];
    const int node = (blockIdx.x * 256 + threadIdx.x) >> 5;
    const int lane = threadIdx.x & 31;
    const int wid  = threadIdx.x >> 5;
    const int deg  = g_deg[node];
    const int* __restrict__ cols = g_cols + (size_t)node * MAXDEG;

    const float es = g_h2[node * 20 + 17];
    float4 a0 = {0,0,0,0}, a1 = {0,0,0,0}, a2 = {0,0,0,0}, a3 = {0,0,0,0};
    float ws = 0.f;

    for (int k = lane; k < deg; k += 32) {
        int m = cols[k];
        const float4* r = reinterpret_cast<const float4*>(&g_h2[m * 20]);
        float4 r0 = r[0], r1 = r[1], r2 = r[2], r3 = r[3];
        float ed = g_h2[m * 20 + 16];
        float e = es + ed; e = e > 0.f ? e : 0.2f * e;
        float w = __expf(e);
        ws += w;
        a0.x += w * r0.x; a0.y += w * r0.y; a0.z += w * r0.z; a0.w += w * r0.w;
        a1.x += w * r1.x; a1.y += w * r1.y; a1.z += w * r1.z; a1.w += w * r1.w;
        a2.x += w * r2.x; a2.y += w * r2.y; a2.z += w * r2.z; a2.w += w * r2.w;
        a3.x += w * r3.x; a3.y += w * r3.y; a3.z += w * r3.z; a3.w += w * r3.w;
    }
    float red[17] = {a0.x,a0.y,a0.z,a0.w, a1.x,a1.y,a1.z,a1.w,
                     a2.x,a2.y,a2.z,a2.w, a3.x,a3.y,a3.z,a3.w, ws};
#pragma unroll
    for (int i = 0; i < 17; i++) XOR_RED(red[i]);

    if (lane == 0) {
        float inv = 1.f / red[16];
#pragma unroll
        for (int f = 0; f < 16; f++) {
            float v = red[f] * inv;
            sblk[wid][f] = v > 0.f ? v : 0.f;
        }
    }
    __syncthreads();

    // per-block partial: 8 nodes -> 16 floats (fixed order)
    if (threadIdx.x < 16) {
        float p = 0.f;
#pragma unroll
        for (int w = 0; w < 8; w++) p += sblk[w][threadIdx.x];
        g_part[blockIdx.x * 16 + threadIdx.x] = p;
    }
    __threadfence();
    __syncthreads();
    __shared__ bool isLast;
    if (threadIdx.x == 0)
        isLast = (atomicAdd(&g_counter, 1) == GRID - 1);
    __syncthreads();
    if (isLast) {
        __threadfence();
        int f = threadIdx.x & 15, g = threadIdx.x >> 4;
        float s = 0.f;
        for (int b = g; b < GRID; b += 16) s += g_part[b * 16 + f];
        __shared__ float red2[256];
        red2[threadIdx.x] = s;
        __syncthreads();
        if (threadIdx.x < 16) {
            float t = 0.f;
#pragma unroll
            for (int gg = 0; gg < 16; gg++) t += red2[gg * 16 + threadIdx.x];
            out[threadIdx.x] = t;
        }
        if (threadIdx.x == 0) g_counter = 0;   // reset for next replay
    }
}

// ---------------- launch ----------------------------------------------------
extern "C" void kernel_launch(void* const* d_in, const int* in_sizes, int n_in,
                              void* d_out, int out_size) {
    const float* x   = (const float*)d_in[0];
    const float* adj = (const float*)d_in[1];
    const float* W0  = (const float*)d_in[2];
    const float* a0s = (const float*)d_in[3];
    const float* a0d = (const float*)d_in[4];
    const float* W1  = (const float*)d_in[5];
    const float* a1s = (const float*)d_in[6];
    const float* a1d = (const float*)d_in[7];
    const float* W2  = (const float*)d_in[8];
    const float* a2s = (const float*)d_in[9];
    const float* a2d = (const float*)d_in[10];
    float* out = (float*)d_out;

    k_csr_lin0 <<<GRID, 256>>>(x, adj, W0, a0s, a0d);
    k_attn0    <<<GRID, 256>>>(W1, a1s, a1d);
    k_attn1    <<<GRID, 256>>>(W2, a2s, a2d);
    k_attn_final<<<GRID, 256>>>(out);
}